// round 14
// baseline (speedup 1.0000x reference)
#include <cuda_runtime.h>
#include <math.h>

namespace {
constexpr int Bn = 8, Cn = 4, Hn = 256, Wn = 256;
constexpr int NPIX = Bn * Hn * Wn;   // 524288
constexpr int TPB = 256;
constexpr int NBLK = NPIX / TPB;     // 2048 (one block == one image row)
constexpr int NSLOT = 256;           // > max smid (152)
}

__device__ double g_part[NSLOT];     // zero-init at load; self-reset each run
__device__ unsigned g_count;

__device__ __forceinline__ unsigned smid() {
    unsigned r; asm("mov.u32 %0, %%smid;" : "=r"(r)); return r;
}

// Smallest k >= kstart with mask(h+-k, w) != c (clamped probes read c); 512 cap.
__device__ __forceinline__ int vdist_from(const int* __restrict__ mask, int base,
                                          int h, int w, int c, int is64, int kstart) {
    int g0 = 512;
    const int lim_u = h, lim_d = Hn - 1 - h;
    const int lim = (lim_u > lim_d) ? lim_u : lim_d;
    bool done = false;
#pragma unroll 1
    for (int kb = kstart; kb <= lim && !done; kb += 4) {
        int uu[4], dd[4];
#pragma unroll
        for (int j = 0; j < 4; ++j) {
            int k = kb + j;
            int hu = (k <= lim_u) ? h - k : h;
            int hd = (k <= lim_d) ? h + k : h;
            uu[j] = __ldg(mask + ((base + hu * Wn + w) << is64));
            dd[j] = __ldg(mask + ((base + hd * Wn + w) << is64));
        }
#pragma unroll
        for (int j = 0; j < 4; ++j)
            if (!done && (uu[j] != c || dd[j] != c)) { g0 = kb + j; done = true; }
    }
    return g0;
}

__global__ __launch_bounds__(TPB, 8)
void boundary_loss_kernel(const float* __restrict__ pred,
                          const int* __restrict__ mask,
                          float* __restrict__ out, int out_n) {
    const unsigned FULL = 0xFFFFFFFFu;
    __shared__ unsigned s_cnt;
    if (threadIdx.x == 0) s_cnt = 0;
    __syncthreads();   // all warps at instr 0: ~7 cyc, no phase coupling

    const int lane = threadIdx.x & 31;
    const int w = threadIdx.x;                 // TPB == Wn; block == one row
    const int b = blockIdx.x >> 8;
    const int h = blockIdx.x & (Hn - 1);
    const int base = b * (Hn * Wn);
    const bool interior = (h >= 4) && (h <= Hn - 5);

    // ---- ONE load round: probe + 9-row own-column window + 3 preds ----
    const int probe = __ldg(mask + 2 * lane + 1);
    int arr[9];                                // rows h-4 .. h+4
    if (interior) {
        const int a0 = base + (h - 4) * Wn + w;
#pragma unroll
        for (int i = 0; i < 9; ++i) arr[i] = __ldg(mask + a0 + i * Wn);
    } else {
#pragma unroll
        for (int i = 0; i < 9; ++i) {
            int hr = h - 4 + i;
            hr = (hr < 0) ? 0 : ((hr > Hn - 1) ? Hn - 1 : hr);
            arr[i] = __ldg(mask + base + hr * Wn + w);
        }
    }
    const float* pp = pred + b * Cn * Hn * Wn + h * Wn + w;
    float pr0 = __ldg(pp + 1 * Hn * Wn);
    float pr1 = __ldg(pp + 2 * Hn * Wn);
    float pr2 = __ldg(pp + 3 * Hn * Wn);

    // int64 storage => all odd 32-bit words zero (fp prob 4^-32): reload.
    const int is64 = __all_sync(FULL, probe == 0) ? 1 : 0;
    if (is64) {
#pragma unroll
        for (int i = 0; i < 9; ++i) {
            int hr = h - 4 + i;
            hr = (hr < 0) ? 0 : ((hr > Hn - 1) ? Hn - 1 : hr);
            arr[i] = __ldg(mask + 2 * (base + hr * Wn + w));
        }
    }
    const int c = arr[4];
    const float p = (c == 0) ? 0.0f : ((c == 1) ? pr0 : (c == 2) ? pr1 : pr2);

    // ---- vertical distance (k<=4 from window, rare deep fallback) ----
    float g2 = 0.0f;
    int pk = 0;
    if (c != 0) {
        int bits = 0;
        if (interior) {
#pragma unroll
            for (int j = 1; j <= 4; ++j)
                bits |= ((arr[4 - j] != c) | (arr[4 + j] != c)) << (j - 1);
        } else {
#pragma unroll
            for (int j = 1; j <= 4; ++j) {
                int uv = (j <= h) ? arr[4 - j] : c;
                int dv = (h + j < Hn) ? arr[4 + j] : c;
                bits |= ((uv != c) | (dv != c)) << (j - 1);
            }
        }
        int g0 = bits ? __ffs(bits) : vdist_from(mask, base, h, w, c, is64, 5);
        int gg = g0 * g0;
        g2 = (float)gg;
        pk = (c << 20) | gg;
    }

    // ---- in-warp exact envelope via shuffles (segment = 32 columns) ----
    float m = g2;
#pragma unroll 1
    for (int r = 1; r < 32; ++r) {
        bool act = (c != 0) && ((float)(r * r) < m);
        if (!__any_sync(FULL, act)) break;
        int pkl = __shfl_up_sync(FULL, pk, r);     // lane-r
        int pkr = __shfl_down_sync(FULL, pk, r);   // lane+r
        if (act) {
            float r2 = (float)(r * r);
            if (r <= lane) {
                float g = ((pkl >> 20) == c) ? (float)(pkl & 0xFFFFF) : 0.0f;
                m = fminf(m, g + r2);
            }
            if (lane + r < 32) {
                float g = ((pkr >> 20) == c) ? (float)(pkr & 0xFFFFF) : 0.0f;
                m = fminf(m, g + r2);
            }
        }
    }

    // ---- cross-segment candidates (rare): recompute from L1-hot global ----
    if (c != 0) {
        const int rowb = base + h * Wn;
#pragma unroll 1
        for (int r = lane + 1; ; ++r) {            // leftward, out of segment
            int x = w - r;
            float r2 = (float)(r * r);
            if (x < 0 || r2 >= m) break;
            int mc = __ldg(mask + ((rowb + x) << is64));
            float g = 0.0f;
            if (mc == c) {
                int gv = vdist_from(mask, base, h, x, c, is64, 1);
                g = (float)(gv * gv);
            }
            m = fminf(m, g + r2);
        }
#pragma unroll 1
        for (int r = 32 - lane; ; ++r) {           // rightward, out of segment
            int x = w + r;
            float r2 = (float)(r * r);
            if (x >= Wn || r2 >= m) break;
            int mc = __ldg(mask + ((rowb + x) << is64));
            float g = 0.0f;
            if (mc == c) {
                int gv = vdist_from(mask, base, h, x, c, is64, 1);
                g = (float)(gv * gv);
            }
            m = fminf(m, g + r2);
        }
    }

    const float norm = (float)(sqrt((double)(Hn * Hn + Wn * Wn)) + 1e-6);
    float term = (c != 0) ? p * (sqrtf(m) / norm) : 0.0f;

    // ---- warp reduce -> per-SM slot; hierarchical completion detection ----
#pragma unroll
    for (int o = 16; o > 0; o >>= 1)
        term += __shfl_down_sync(FULL, term, o);

    unsigned wprev = 0;
    if (lane == 0) {
        atomicAdd(&g_part[smid()], (double)term);
        __threadfence();                      // g_part add visible before s_cnt
        wprev = atomicAdd(&s_cnt, 1u);        // shared atomic, ~32 cyc
    }
    wprev = __shfl_sync(FULL, wprev, 0);
    if (wprev == (TPB / 32) - 1) {            // last warp of this block
        unsigned bprev = 0;
        if (lane == 0) {
            __threadfence();
            bprev = atomicAdd(&g_count, 1u);  // 2048 total, R8-proven scale
        }
        bprev = __shfl_sync(FULL, bprev, 0);
        if (bprev == (unsigned)(NBLK - 1)) {  // last block: warp-parallel sum
            double s = 0.0;
#pragma unroll
            for (int j = 0; j < NSLOT / 32; ++j) {
                int i = lane + 32 * j;
                s += __ldcg(&g_part[i]);      // batched L2 reads (MLP=8)
                __stcg(&g_part[i], 0.0);      // reset for next graph replay
            }
#pragma unroll
            for (int o = 16; o > 0; o >>= 1)
                s += __shfl_down_sync(FULL, s, o);
            if (lane == 0) {
                float r = (float)(s / ((double)NPIX * (Cn - 1)));
                for (int i = 0; i < out_n; ++i) out[i] = r;
                g_count = 0u;
            }
        }
    }
}

extern "C" void kernel_launch(void* const* d_in, const int* in_sizes, int n_in,
                              void* d_out, int out_size) {
    const float* pred;
    const int* mask;
    if (in_sizes[0] >= in_sizes[1]) {
        pred = (const float*)d_in[0];
        mask = (const int*)d_in[1];
    } else {
        pred = (const float*)d_in[1];
        mask = (const int*)d_in[0];
    }
    boundary_loss_kernel<<<NBLK, TPB>>>(pred, mask, (float*)d_out, out_size);
}

// round 15
// speedup vs baseline: 1.2275x; 1.2275x over previous
#include <cuda_runtime.h>
#include <math.h>

namespace {
constexpr int Bn = 8, Cn = 4, Hn = 256, Wn = 256;
constexpr int NPIX = Bn * Hn * Wn;   // 524288
constexpr int TPB = 256;
constexpr int NBLK = NPIX / TPB;     // 2048 (one block == one image row)
}

__device__ double g_acc;      // zero-init at module load; self-reset each run
__device__ unsigned g_count;

// Smallest k >= kstart with mask(h+-k, w) != c (clamped probes read c); 512 cap.
__device__ __forceinline__ int vdist_from(const int* __restrict__ mask, int base,
                                          int h, int w, int c, int is64, int kstart) {
    int g0 = 512;
    const int lim_u = h, lim_d = Hn - 1 - h;
    const int lim = (lim_u > lim_d) ? lim_u : lim_d;
    bool done = false;
#pragma unroll 1
    for (int kb = kstart; kb <= lim && !done; kb += 4) {
        int uu[4], dd[4];
#pragma unroll
        for (int j = 0; j < 4; ++j) {
            int k = kb + j;
            int hu = (k <= lim_u) ? h - k : h;
            int hd = (k <= lim_d) ? h + k : h;
            uu[j] = __ldg(mask + ((base + hu * Wn + w) << is64));
            dd[j] = __ldg(mask + ((base + hd * Wn + w) << is64));
        }
#pragma unroll
        for (int j = 0; j < 4; ++j)
            if (!done && (uu[j] != c || dd[j] != c)) { g0 = kb + j; done = true; }
    }
    return g0;
}

__global__ __launch_bounds__(TPB, 8)
void boundary_loss_kernel(const float* __restrict__ pred,
                          const int* __restrict__ mask,
                          float* __restrict__ out, int out_n) {
    const unsigned FULL = 0xFFFFFFFFu;
    __shared__ float ws[TPB / 32];

    const int lane = threadIdx.x & 31;
    const int w = threadIdx.x;                 // TPB == Wn; block == one row
    const int b = blockIdx.x >> 8;
    const int h = blockIdx.x & (Hn - 1);
    const int base = b * (Hn * Wn);
    const bool interior = (h >= 4) && (h <= Hn - 5);

    // ---- ONE load round: probe + 9-row own-column window + 3 preds ----
    const int probe = __ldg(mask + 2 * lane + 1);
    int arr[9];                                // rows h-4 .. h+4
    if (interior) {
        const int a0 = base + (h - 4) * Wn + w;
#pragma unroll
        for (int i = 0; i < 9; ++i) arr[i] = __ldg(mask + a0 + i * Wn);
    } else {
#pragma unroll
        for (int i = 0; i < 9; ++i) {
            int hr = h - 4 + i;
            hr = (hr < 0) ? 0 : ((hr > Hn - 1) ? Hn - 1 : hr);
            arr[i] = __ldg(mask + base + hr * Wn + w);
        }
    }
    const float* pp = pred + b * Cn * Hn * Wn + h * Wn + w;
    float pr0 = __ldg(pp + 1 * Hn * Wn);
    float pr1 = __ldg(pp + 2 * Hn * Wn);
    float pr2 = __ldg(pp + 3 * Hn * Wn);

    // int64 storage => all odd 32-bit words zero (fp prob 4^-32): reload.
    const int is64 = __all_sync(FULL, probe == 0) ? 1 : 0;
    if (is64) {
#pragma unroll
        for (int i = 0; i < 9; ++i) {
            int hr = h - 4 + i;
            hr = (hr < 0) ? 0 : ((hr > Hn - 1) ? Hn - 1 : hr);
            arr[i] = __ldg(mask + 2 * (base + hr * Wn + w));
        }
    }
    const int c = arr[4];
    const float p = (c == 0) ? 0.0f : ((c == 1) ? pr0 : (c == 2) ? pr1 : pr2);

    // ---- vertical distance (k<=4 from window, rare deep fallback) ----
    float g2 = 0.0f;
    int pk = 0;
    if (c != 0) {
        int bits = 0;
        if (interior) {
#pragma unroll
            for (int j = 1; j <= 4; ++j)
                bits |= ((arr[4 - j] != c) | (arr[4 + j] != c)) << (j - 1);
        } else {
#pragma unroll
            for (int j = 1; j <= 4; ++j) {
                int uv = (j <= h) ? arr[4 - j] : c;
                int dv = (h + j < Hn) ? arr[4 + j] : c;
                bits |= ((uv != c) | (dv != c)) << (j - 1);
            }
        }
        int g0 = bits ? __ffs(bits) : vdist_from(mask, base, h, w, c, is64, 5);
        int gg = g0 * g0;
        g2 = (float)gg;
        pk = (c << 20) | gg;
    }

    // ---- in-warp exact envelope via shuffles (segment = 32 columns) ----
    float m = g2;
#pragma unroll 1
    for (int r = 1; r < 32; ++r) {
        bool act = (c != 0) && ((float)(r * r) < m);
        if (!__any_sync(FULL, act)) break;
        int pkl = __shfl_up_sync(FULL, pk, r);     // lane-r
        int pkr = __shfl_down_sync(FULL, pk, r);   // lane+r
        if (act) {
            float r2 = (float)(r * r);
            if (r <= lane) {
                float g = ((pkl >> 20) == c) ? (float)(pkl & 0xFFFFF) : 0.0f;
                m = fminf(m, g + r2);
            }
            if (lane + r < 32) {
                float g = ((pkr >> 20) == c) ? (float)(pkr & 0xFFFFF) : 0.0f;
                m = fminf(m, g + r2);
            }
        }
    }

    // ---- cross-segment candidates (rare): recompute from L1-hot global ----
    if (c != 0) {
        const int rowb = base + h * Wn;
#pragma unroll 1
        for (int r = lane + 1; ; ++r) {            // leftward, out of segment
            int x = w - r;
            float r2 = (float)(r * r);
            if (x < 0 || r2 >= m) break;
            int mc = __ldg(mask + ((rowb + x) << is64));
            float g = 0.0f;
            if (mc == c) {
                int gv = vdist_from(mask, base, h, x, c, is64, 1);
                g = (float)(gv * gv);
            }
            m = fminf(m, g + r2);
        }
#pragma unroll 1
        for (int r = 32 - lane; ; ++r) {           // rightward, out of segment
            int x = w + r;
            float r2 = (float)(r * r);
            if (x >= Wn || r2 >= m) break;
            int mc = __ldg(mask + ((rowb + x) << is64));
            float g = 0.0f;
            if (mc == c) {
                int gv = vdist_from(mask, base, h, x, c, is64, 1);
                g = (float)(gv * gv);
            }
            m = fminf(m, g + r2);
        }
    }

    const float norm = (float)(sqrt((double)(Hn * Hn + Wn * Wn)) + 1e-6);
    float term = (c != 0) ? p * (sqrtf(m) / norm) : 0.0f;

    // ---- tail: block reduce (end-of-kernel barrier), ONE fence/atomic per block ----
#pragma unroll
    for (int o = 16; o > 0; o >>= 1)
        term += __shfl_down_sync(FULL, term, o);
    if (lane == 0) ws[threadIdx.x >> 5] = term;
    __syncthreads();
    if (threadIdx.x < TPB / 32) {
        float v = ws[threadIdx.x];
#pragma unroll
        for (int o = 4; o > 0; o >>= 1)
            v += __shfl_down_sync(0xFFu, v, o);
        if (threadIdx.x == 0) {
            atomicAdd(&g_acc, (double)v);
            __threadfence();  // one per block: order g_acc add before count bump
            unsigned prev = atomicAdd(&g_count, 1u);
            if (prev == (unsigned)(NBLK - 1)) {
                double total = atomicAdd(&g_acc, 0.0);  // L2-coherent read
                float r = (float)(total / ((double)NPIX * (Cn - 1)));
                for (int i = 0; i < out_n; ++i) out[i] = r;
                g_acc = 0.0;   // reset for next graph replay (deterministic)
                g_count = 0u;
            }
        }
    }
}

extern "C" void kernel_launch(void* const* d_in, const int* in_sizes, int n_in,
                              void* d_out, int out_size) {
    const float* pred;
    const int* mask;
    if (in_sizes[0] >= in_sizes[1]) {
        pred = (const float*)d_in[0];
        mask = (const int*)d_in[1];
    } else {
        pred = (const float*)d_in[1];
        mask = (const int*)d_in[0];
    }
    boundary_loss_kernel<<<NBLK, TPB>>>(pred, mask, (float*)d_out, out_size);
}